// round 9
// baseline (speedup 1.0000x reference)
#include <cuda_runtime.h>
#include <cuda_fp16.h>
#include <cstdint>

// ---------------- smem layout (bytes) ----------------
#define B_SPLIT  25600          // 160 k-pairs x 160B (word (e>>1)*160 + j*4 + (e&1)*2)
#define SB_B     0
#define SB_THR   51200          // 32 floats
#define SB_WAON  51328          // 32 floats
#define SMEM_TOT 51456

__device__ float g_ctable[50048];

__device__ __forceinline__ uint32_t h2u(__half2 h) {
    union { __half2 h; uint32_t u; } cv; cv.h = h; return cv.u;
}

// 2-limb fp16 split of a k-consecutive pair -> two fragment words
__device__ __forceinline__ void split2pack(float2 v, uint32_t& s0, uint32_t& s1) {
    __half2 h0 = __float22half2_rn(v);
    float2 f0 = __half22float2(h0);
    __half2 h1 = __float22half2_rn(make_float2(v.x - f0.x, v.y - f0.y));
    s0 = h2u(h0);
    s1 = h2u(h1);
}

__device__ __forceinline__ void mma16816(float* d, const uint32_t* a, const uint32_t* b) {
    asm volatile(
        "mma.sync.aligned.m16n8k16.row.col.f32.f16.f16.f32 "
        "{%0,%1,%2,%3}, {%4,%5,%6,%7}, {%8,%9}, {%0,%1,%2,%3};"
        : "+f"(d[0]), "+f"(d[1]), "+f"(d[2]), "+f"(d[3])
        : "r"(a[0]), "r"(a[1]), "r"(a[2]), "r"(a[3]), "r"(b[0]), "r"(b[1]));
}

__device__ __forceinline__ float2 ldw2(const float* p, bool ok) {
    return ok ? __ldg((const float2*)p) : make_float2(0.f, 0.f);
}

// ---------------- vocab GEMM: 4 warps x 32 rows, direct-fragment LDG ----------------
__global__ __launch_bounds__(128, 4) void vocab_mma(const float* __restrict__ w_emb,
                                                    const float* __restrict__ a_emb,
                                                    const float* __restrict__ a_wt,
                                                    int V) {
    extern __shared__ char smem[];
    const int tid = threadIdx.x, lane = tid & 31, wid = tid >> 5;
    const int g = lane >> 2, t = lane & 3;          // mma fragment mapping

    // 1) zero B splits + pads
    for (int i = tid; i < 2 * B_SPLIT / 16; i += 128)
        *(uint4*)(smem + SB_B + i * 16) = make_uint4(0, 0, 0, 0);
    if (tid < 32) {
        *(float*)(smem + SB_THR + tid * 4) = 3.0e38f;
        *(float*)(smem + SB_WAON + tid * 4) = 0.f;
    }
    __syncthreads();

    // 2) fill B (aspects): element (k=e, n=j) -> word (e>>1)*160 + j*4 (+2 if e odd)
    for (int idx = tid; idx < 30 * 300; idx += 128) {
        int j = idx / 300, e = idx - j * 300;
        float f = a_emb[idx];
        __half h0 = __float2half_rn(f);
        __half h1 = __float2half_rn(f - __half2float(h0));
        uint32_t base = (uint32_t)((e >> 1) * 160 + j * 4 + (e & 1) * 2);
        *(__half*)(smem + SB_B + base)           = h0;
        *(__half*)(smem + SB_B + B_SPLIT + base) = h1;
    }

    // 3) aspect norms -> thr/waon (4 lanes per aspect)
    {
        int j = tid >> 2, e4 = tid & 3;
        int jj = (j < 30) ? j : 0;
        float s = 0.f;
        for (int e = e4; e < 300; e += 4) { float v = a_emb[jj * 300 + e]; s = fmaf(v, v, s); }
        s += __shfl_xor_sync(0xffffffffu, s, 1);
        s += __shfl_xor_sync(0xffffffffu, s, 2);
        if (j < 30 && e4 == 0) {
            float an = fmaxf(sqrtf(s), 1e-8f);
            *(float*)(smem + SB_THR + j * 4)  = 0.2f * an;
            *(float*)(smem + SB_WAON + j * 4) = a_wt[j] / an;
        }
    }
    __syncthreads();

    // 4) row pointers: rows u = 0..3 -> wid*32 + u*8 + g  (tiles: ti=u>>1)
    int grow[4]; bool rok[4];
    const float* p[4];
#pragma unroll
    for (int u = 0; u < 4; u++) {
        grow[u] = blockIdx.x * 128 + wid * 32 + u * 8 + g;
        rok[u]  = grow[u] < V;
        p[u]    = w_emb + (size_t)(rok[u] ? grow[u] : 0) * 300 + 2 * t;
    }

    float d[2][4][4];
#pragma unroll
    for (int ti = 0; ti < 2; ti++)
#pragma unroll
        for (int nt = 0; nt < 4; nt++)
#pragma unroll
            for (int i = 0; i < 4; i++) d[ti][nt][i] = 0.f;
    float nrm[4] = {0.f, 0.f, 0.f, 0.f};

    // register prefetch k16 = 0: cur[2u] = lo pair, cur[2u+1] = hi pair
    float2 cur[8];
#pragma unroll
    for (int u = 0; u < 4; u++) {
        cur[2 * u]     = ldw2(p[u],     rok[u]);
        cur[2 * u + 1] = ldw2(p[u] + 8, rok[u]);
    }

#pragma unroll 1
    for (int k16 = 0; k16 < 19; k16++) {
        // prefetch next step (hi-pair OOB at last step for t>=2)
        float2 nx[8];
#pragma unroll
        for (int i = 0; i < 8; i++) nx[i] = make_float2(0.f, 0.f);
        if (k16 < 18) {
            bool hok = (k16 + 1 < 18) | (t < 2);
#pragma unroll
            for (int u = 0; u < 4; u++) {
                const float* q = p[u] + (k16 + 1) * 16;
                nx[2 * u]     = ldw2(q,     rok[u]);
                nx[2 * u + 1] = ldw2(q + 8, rok[u] & hok);
            }
        }

        // B fragments (conflict-free LDS.32, round-7 layout)
        uint32_t bf[2][4][2];
        uint32_t sbase = (uint32_t)((k16 * 8 + t) * 160 + g * 4);
#pragma unroll
        for (int s = 0; s < 2; s++) {
            uint32_t sb = SB_B + (uint32_t)s * B_SPLIT + sbase;
#pragma unroll
            for (int nt = 0; nt < 4; nt++) {
                bf[s][nt][0] = *(const uint32_t*)(smem + sb + nt * 32);
                bf[s][nt][1] = *(const uint32_t*)(smem + sb + nt * 32 + 640);
            }
        }

        // two m16 tiles share the B fragments
#pragma unroll
        for (int ti = 0; ti < 2; ti++) {
            int u0 = ti * 2, u1 = ti * 2 + 1;
            uint32_t af[2][4];
            split2pack(cur[2 * u0],     af[0][0], af[1][0]);  // row u0, k lo
            split2pack(cur[2 * u1],     af[0][1], af[1][1]);  // row u1, k lo
            split2pack(cur[2 * u0 + 1], af[0][2], af[1][2]);  // row u0, k hi
            split2pack(cur[2 * u1 + 1], af[0][3], af[1][3]);  // row u1, k hi
#pragma unroll
            for (int nt = 0; nt < 4; nt++) {
                mma16816(d[ti][nt], af[0], bf[0][nt]);   // w0*a0
                mma16816(d[ti][nt], af[0], bf[1][nt]);   // w0*a1
                mma16816(d[ti][nt], af[1], bf[0][nt]);   // w1*a0
            }
        }

        // norms + rotate prefetch
#pragma unroll
        for (int u = 0; u < 4; u++) {
            float2 lo = cur[2 * u], hi = cur[2 * u + 1];
            nrm[u] = fmaf(lo.x, lo.x, nrm[u]); nrm[u] = fmaf(lo.y, lo.y, nrm[u]);
            nrm[u] = fmaf(hi.x, hi.x, nrm[u]); nrm[u] = fmaf(hi.y, hi.y, nrm[u]);
        }
#pragma unroll
        for (int i = 0; i < 8; i++) cur[i] = nx[i];
    }

    // reduce norms over the 4 t-lanes
    float nxr[4];
#pragma unroll
    for (int u = 0; u < 4; u++) {
        float n = nrm[u];
        n += __shfl_xor_sync(0xffffffffu, n, 1);
        n += __shfl_xor_sync(0xffffffffu, n, 2);
        nxr[u] = fmaxf(sqrtf(n), 1e-8f);
    }

    // epilogue: threshold + max over aspects; d[ti][nt][0,1]->u=2ti, [2,3]->u=2ti+1
    float best[4] = {0.f, 0.f, 0.f, 0.f};
#pragma unroll
    for (int nt = 0; nt < 4; nt++) {
        int j0 = nt * 8 + 2 * t, j1 = j0 + 1;
        float th0 = *(const float*)(smem + SB_THR + j0 * 4);
        float th1 = *(const float*)(smem + SB_THR + j1 * 4);
        float w0  = *(const float*)(smem + SB_WAON + j0 * 4);
        float w1  = *(const float*)(smem + SB_WAON + j1 * 4);
#pragma unroll
        for (int ti = 0; ti < 2; ti++) {
            int ua = 2 * ti, ub = 2 * ti + 1;
            if (d[ti][nt][0] > th0 * nxr[ua]) best[ua] = fmaxf(best[ua], d[ti][nt][0] * w0);
            if (d[ti][nt][1] > th1 * nxr[ua]) best[ua] = fmaxf(best[ua], d[ti][nt][1] * w1);
            if (d[ti][nt][2] > th0 * nxr[ub]) best[ub] = fmaxf(best[ub], d[ti][nt][2] * w0);
            if (d[ti][nt][3] > th1 * nxr[ub]) best[ub] = fmaxf(best[ub], d[ti][nt][3] * w1);
        }
    }
#pragma unroll
    for (int u = 0; u < 4; u++) {
        float b = best[u];
        b = fmaxf(b, __shfl_xor_sync(0xffffffffu, b, 1));
        b = fmaxf(b, __shfl_xor_sync(0xffffffffu, b, 2));
        if (t == 0 && rok[u]) g_ctable[grow[u]] = b / nxr[u];
    }
}

// ---------------- row kernel ----------------
__global__ __launch_bounds__(256) void row_kernel(const int* __restrict__ tokens,
                                                  const float* __restrict__ w_emb,
                                                  float* __restrict__ enc,
                                                  float* __restrict__ attn,
                                                  float* __restrict__ cscore,
                                                  int L, int E) {
    int b = blockIdx.x;
    int l = threadIdx.x;
    int lane = l & 31, wid = l >> 5;

    __shared__ float red_m[8], red_s[8];
    __shared__ int   red_n[8];
    __shared__ float bc_max, bc_cs, bc_den;
    __shared__ int   s_woff[8], s_n;
    __shared__ int   s_tok[256];
    __shared__ float s_w[256];

    int tok   = tokens[(size_t)b * L + l];
    float c   = g_ctable[tok];
    float score = (c > 0.f) ? c : -1e9f;
    int   cnt = (tok != 0) ? 1 : 0;

    float m = score, sc = c; int cn = cnt;
#pragma unroll
    for (int o = 16; o; o >>= 1) {
        m  = fmaxf(m, __shfl_xor_sync(0xffffffffu, m, o));
        sc += __shfl_xor_sync(0xffffffffu, sc, o);
        cn += __shfl_xor_sync(0xffffffffu, cn, o);
    }
    if (lane == 0) { red_m[wid] = m; red_s[wid] = sc; red_n[wid] = cn; }
    __syncthreads();
    if (l == 0) {
        float M = red_m[0], S = red_s[0]; int N = red_n[0];
#pragma unroll
        for (int i = 1; i < 8; i++) { M = fmaxf(M, red_m[i]); S += red_s[i]; N += red_n[i]; }
        bc_max = M;
        bc_cs  = S / ((float)N + 1e-5f);
    }
    __syncthreads();

    float M  = bc_max;
    float cs = bc_cs;
    float e  = expf(score - M);

    float se = e;
#pragma unroll
    for (int o = 16; o; o >>= 1) se += __shfl_xor_sync(0xffffffffu, se, o);
    if (lane == 0) red_s[wid] = se;
    __syncthreads();
    if (l == 0) {
        float D = red_s[0];
#pragma unroll
        for (int i = 1; i < 8; i++) D += red_s[i];
        bc_den = D;
    }
    __syncthreads();

    float a = e / bc_den;
    attn[(size_t)b * L + l] = a;
    if (l == 0) cscore[b] = cs;

    bool gate = cs > 1e-4f;
    if (gate) {
        bool act = (e > 0.f);
        unsigned mask = __ballot_sync(0xffffffffu, act);
        if (lane == 0) s_woff[wid] = __popc(mask);
        __syncthreads();
        if (l == 0) {
            int o = 0;
#pragma unroll
            for (int i = 0; i < 8; i++) { int tt = s_woff[i]; s_woff[i] = o; o += tt; }
            s_n = o;
        }
        __syncthreads();
        if (act) {
            int pos = s_woff[wid] + __popc(mask & ((1u << lane) - 1u));
            s_tok[pos] = tok;
            s_w[pos]   = a;
        }
        __syncthreads();
        int n = s_n;
        for (int j = l; j < E; j += 256) {
            float z = 0.f;
            for (int i = 0; i < n; i++)
                z = fmaf(s_w[i], w_emb[(size_t)s_tok[i] * E + j], z);
            enc[(size_t)b * E + j] = z;
        }
    } else {
        for (int j = l; j < E; j += 256)
            enc[(size_t)b * E + j] = 0.f;
    }
}

// ---------------- launch ----------------
extern "C" void kernel_launch(void* const* d_in, const int* in_sizes, int n_in,
                              void* d_out, int out_size) {
    const int*   inputs = (const int*)d_in[0];     // [B, L]
    const float* w_emb  = (const float*)d_in[1];   // [V, E]
    const float* a_emb  = (const float*)d_in[2];   // [A, E]
    const float* a_w    = (const float*)d_in[3];   // [A]

    int BL = in_sizes[0];
    int A  = in_sizes[3];
    int E  = in_sizes[2] / A;        // 300
    int V  = in_sizes[1] / E;        // 50000
    int L  = 256;
    int B  = BL / L;                 // 1024

    static bool attr_set = false;
    if (!attr_set) {
        cudaFuncSetAttribute(vocab_mma, cudaFuncAttributeMaxDynamicSharedMemorySize, SMEM_TOT);
        attr_set = true;
    }

    vocab_mma<<<(V + 127) / 128, 128, SMEM_TOT>>>(w_emb, a_emb, a_w, V);

    float* out    = (float*)d_out;
    float* enc    = out;                                   // [B, E]
    float* attn   = out + (size_t)B * E;                   // [B, L]
    float* cscore = out + (size_t)B * E + (size_t)B * L;   // [B]
    row_kernel<<<B, 256>>>(inputs, w_emb, enc, attn, cscore, L, E);
}

// round 10
// speedup vs baseline: 1.1355x; 1.1355x over previous
#include <cuda_runtime.h>
#include <cuda_fp16.h>
#include <cstdint>

// ---------------- smem layout (bytes) ----------------
#define B_SPLIT  25600          // 160 k-pairs x 160B
#define SB_B     0
#define SB_THR   51200          // 32 floats
#define SB_WAON  51328          // 32 floats
#define SMEM_TOT 51456

__device__ float g_ctable[50048];

__device__ __forceinline__ uint32_t h2u(__half2 h) {
    union { __half2 h; uint32_t u; } cv; cv.h = h; return cv.u;
}
__device__ __forceinline__ float2 u2f2(uint32_t u) {
    union { uint32_t u; __half2 h; } cv; cv.u = u;
    return __half22float2(cv.h);
}

// 2-limb fp16 split of a k-consecutive pair -> two fragment words
__device__ __forceinline__ void split2pack(float2 v, uint32_t& s0, uint32_t& s1) {
    __half2 h0 = __float22half2_rn(v);
    float2 f0 = __half22float2(h0);
    __half2 h1 = __float22half2_rn(make_float2(v.x - f0.x, v.y - f0.y));
    s0 = h2u(h0);
    s1 = h2u(h1);
}

__device__ __forceinline__ void mma16816(float* d, const uint32_t* a, const uint32_t* b) {
    asm volatile(
        "mma.sync.aligned.m16n8k16.row.col.f32.f16.f16.f32 "
        "{%0,%1,%2,%3}, {%4,%5,%6,%7}, {%8,%9}, {%0,%1,%2,%3};"
        : "+f"(d[0]), "+f"(d[1]), "+f"(d[2]), "+f"(d[3])
        : "r"(a[0]), "r"(a[1]), "r"(a[2]), "r"(a[3]), "r"(b[0]), "r"(b[1]));
}
// fp16-accumulate variant for the small correction terms
__device__ __forceinline__ void mma16816h(uint32_t* c, const uint32_t* a, const uint32_t* b) {
    asm volatile(
        "mma.sync.aligned.m16n8k16.row.col.f16.f16.f16.f16 "
        "{%0,%1}, {%2,%3,%4,%5}, {%6,%7}, {%0,%1};"
        : "+r"(c[0]), "+r"(c[1])
        : "r"(a[0]), "r"(a[1]), "r"(a[2]), "r"(a[3]), "r"(b[0]), "r"(b[1]));
}

__device__ __forceinline__ float2 ldw2(const float* p, bool ok) {
    return ok ? __ldg((const float2*)p) : make_float2(0.f, 0.f);
}

// ---------------- vocab GEMM (round-7 structure + fp16-acc corrections) ----------------
__global__ __launch_bounds__(256, 3) void vocab_mma(const float* __restrict__ w_emb,
                                                    const float* __restrict__ a_emb,
                                                    const float* __restrict__ a_wt,
                                                    int V) {
    extern __shared__ char smem[];
    const int tid = threadIdx.x, lane = tid & 31, wid = tid >> 5;
    const int g = lane >> 2, t = lane & 3;          // mma fragment mapping

    for (int i = tid; i < 2 * B_SPLIT / 16; i += 256)
        *(uint4*)(smem + SB_B + i * 16) = make_uint4(0, 0, 0, 0);
    if (tid < 32) {
        *(float*)(smem + SB_THR + tid * 4) = 3.0e38f;
        *(float*)(smem + SB_WAON + tid * 4) = 0.f;
    }
    __syncthreads();

    // fill B (aspects): element (k=e, n=j) -> word (e>>1)*160 + j*4 (+2 if e odd)
    for (int idx = tid; idx < 30 * 300; idx += 256) {
        int j = idx / 300, e = idx - j * 300;
        float f = a_emb[idx];
        __half h0 = __float2half_rn(f);
        __half h1 = __float2half_rn(f - __half2float(h0));
        uint32_t base = (uint32_t)((e >> 1) * 160 + j * 4 + (e & 1) * 2);
        *(__half*)(smem + SB_B + base)           = h0;
        *(__half*)(smem + SB_B + B_SPLIT + base) = h1;
    }

    // aspect norms -> thr/waon
    {
        int j = tid >> 3, e8 = tid & 7;
        int jj = (j < 30) ? j : 0;
        float s = 0.f;
        for (int e = e8; e < 300; e += 8) { float v = a_emb[jj * 300 + e]; s = fmaf(v, v, s); }
        s += __shfl_xor_sync(0xffffffffu, s, 1);
        s += __shfl_xor_sync(0xffffffffu, s, 2);
        s += __shfl_xor_sync(0xffffffffu, s, 4);
        if (j < 30 && e8 == 0) {
            float an = fmaxf(sqrtf(s), 1e-8f);
            *(float*)(smem + SB_THR + j * 4)  = 0.2f * an;
            *(float*)(smem + SB_WAON + j * 4) = a_wt[j] / an;
        }
    }
    __syncthreads();

    const int r0 = wid * 16 + g, r1 = r0 + 8;
    const int gr0 = blockIdx.x * 128 + r0, gr1 = blockIdx.x * 128 + r1;
    const bool rok0 = gr0 < V, rok1 = gr1 < V;
    const float* p0 = w_emb + (size_t)(rok0 ? gr0 : 0) * 300 + 2 * t;
    const float* p1 = w_emb + (size_t)(rok1 ? gr1 : 0) * 300 + 2 * t;

    float d[4][4];
    uint32_t hc[4][2];
#pragma unroll
    for (int nt = 0; nt < 4; nt++) {
#pragma unroll
        for (int i = 0; i < 4; i++) d[nt][i] = 0.f;
        hc[nt][0] = 0u; hc[nt][1] = 0u;
    }
    float nrm0 = 0.f, nrm1 = 0.f;

    float2 cur0 = ldw2(p0,      rok0);
    float2 cur1 = ldw2(p0 + 8,  rok0);
    float2 cur2 = ldw2(p1,      rok1);
    float2 cur3 = ldw2(p1 + 8,  rok1);

#pragma unroll 1
    for (int k16 = 0; k16 < 19; k16++) {
        float2 nx0 = make_float2(0.f, 0.f), nx1 = nx0, nx2 = nx0, nx3 = nx0;
        if (k16 < 18) {
            const float* q0 = p0 + (k16 + 1) * 16;
            const float* q1 = p1 + (k16 + 1) * 16;
            bool hok = (k16 + 1 < 18) | (t < 2);
            nx0 = ldw2(q0,     rok0);
            nx1 = ldw2(q0 + 8, rok0 & hok);
            nx2 = ldw2(q1,     rok1);
            nx3 = ldw2(q1 + 8, rok1 & hok);
        }

        uint32_t af[2][4];
        split2pack(cur0, af[0][0], af[1][0]);
        split2pack(cur2, af[0][1], af[1][1]);
        split2pack(cur1, af[0][2], af[1][2]);
        split2pack(cur3, af[0][3], af[1][3]);
        nrm0 = fmaf(cur0.x, cur0.x, nrm0); nrm0 = fmaf(cur0.y, cur0.y, nrm0);
        nrm0 = fmaf(cur1.x, cur1.x, nrm0); nrm0 = fmaf(cur1.y, cur1.y, nrm0);
        nrm1 = fmaf(cur2.x, cur2.x, nrm1); nrm1 = fmaf(cur2.y, cur2.y, nrm1);
        nrm1 = fmaf(cur3.x, cur3.x, nrm1); nrm1 = fmaf(cur3.y, cur3.y, nrm1);

        uint32_t bf[2][4][2];
        uint32_t sbase = (uint32_t)((k16 * 8 + t) * 160 + g * 4);
#pragma unroll
        for (int s = 0; s < 2; s++) {
            uint32_t sb = SB_B + (uint32_t)s * B_SPLIT + sbase;
#pragma unroll
            for (int nt = 0; nt < 4; nt++) {
                bf[s][nt][0] = *(const uint32_t*)(smem + sb + nt * 32);
                bf[s][nt][1] = *(const uint32_t*)(smem + sb + nt * 32 + 640);
            }
        }

#pragma unroll
        for (int nt = 0; nt < 4; nt++) {
            mma16816(d[nt],  af[0], bf[0][nt]);   // w0*a0  (fp32 acc)
            mma16816h(hc[nt], af[0], bf[1][nt]);  // w0*a1  (fp16 acc)
            mma16816h(hc[nt], af[1], bf[0][nt]);  // w1*a0  (fp16 acc)
        }

        cur0 = nx0; cur1 = nx1; cur2 = nx2; cur3 = nx3;
    }

    // fold fp16 corrections into fp32 accumulators
#pragma unroll
    for (int nt = 0; nt < 4; nt++) {
        float2 clo = u2f2(hc[nt][0]);
        float2 chi = u2f2(hc[nt][1]);
        d[nt][0] += clo.x; d[nt][1] += clo.y;
        d[nt][2] += chi.x; d[nt][3] += chi.y;
    }

    nrm0 += __shfl_xor_sync(0xffffffffu, nrm0, 1);
    nrm0 += __shfl_xor_sync(0xffffffffu, nrm0, 2);
    nrm1 += __shfl_xor_sync(0xffffffffu, nrm1, 1);
    nrm1 += __shfl_xor_sync(0xffffffffu, nrm1, 2);
    float nx0 = fmaxf(sqrtf(nrm0), 1e-8f);
    float nx1 = fmaxf(sqrtf(nrm1), 1e-8f);

    float b0 = 0.f, b1 = 0.f;
#pragma unroll
    for (int nt = 0; nt < 4; nt++) {
        int j0 = nt * 8 + 2 * t, j1 = j0 + 1;
        float th0 = *(const float*)(smem + SB_THR + j0 * 4);
        float th1 = *(const float*)(smem + SB_THR + j1 * 4);
        float w0  = *(const float*)(smem + SB_WAON + j0 * 4);
        float w1  = *(const float*)(smem + SB_WAON + j1 * 4);
        if (d[nt][0] > th0 * nx0) b0 = fmaxf(b0, d[nt][0] * w0);
        if (d[nt][1] > th1 * nx0) b0 = fmaxf(b0, d[nt][1] * w1);
        if (d[nt][2] > th0 * nx1) b1 = fmaxf(b1, d[nt][2] * w0);
        if (d[nt][3] > th1 * nx1) b1 = fmaxf(b1, d[nt][3] * w1);
    }
    b0 = fmaxf(b0, __shfl_xor_sync(0xffffffffu, b0, 1));
    b0 = fmaxf(b0, __shfl_xor_sync(0xffffffffu, b0, 2));
    b1 = fmaxf(b1, __shfl_xor_sync(0xffffffffu, b1, 1));
    b1 = fmaxf(b1, __shfl_xor_sync(0xffffffffu, b1, 2));
    if (t == 0) {
        if (rok0) g_ctable[gr0] = b0 / nx0;
        if (rok1) g_ctable[gr1] = b1 / nx1;
    }
}

// ---------------- row kernel: one warp per row, no block barriers ----------------
__global__ __launch_bounds__(128) void row_warp_kernel(const int* __restrict__ tokens,
                                                       const float* __restrict__ w_emb,
                                                       float* __restrict__ enc,
                                                       float* __restrict__ attn,
                                                       float* __restrict__ cscore) {
    const int b    = blockIdx.x * 4 + (threadIdx.x >> 5);
    const int lane = threadIdx.x & 31;
    const int* trow = tokens + (size_t)b * 256;

    int   tok[8];
    float c[8];
#pragma unroll
    for (int i = 0; i < 8; i++) {
        tok[i] = trow[i * 32 + lane];
        c[i]   = g_ctable[tok[i]];
    }

    float m = -1e9f, sc = 0.f; int cn = 0;
#pragma unroll
    for (int i = 0; i < 8; i++) {
        float s = (c[i] > 0.f) ? c[i] : -1e9f;
        m = fmaxf(m, s);
        sc += c[i];
        cn += (tok[i] != 0) ? 1 : 0;
    }
#pragma unroll
    for (int o = 16; o; o >>= 1) {
        m  = fmaxf(m, __shfl_xor_sync(0xffffffffu, m, o));
        sc += __shfl_xor_sync(0xffffffffu, sc, o);
        cn += __shfl_xor_sync(0xffffffffu, cn, o);
    }
    float cs = sc / ((float)cn + 1e-5f);

    float e[8]; float se = 0.f;
#pragma unroll
    for (int i = 0; i < 8; i++) {
        float s = (c[i] > 0.f) ? c[i] : -1e9f;
        e[i] = expf(s - m);
        se += e[i];
    }
#pragma unroll
    for (int o = 16; o; o >>= 1) se += __shfl_xor_sync(0xffffffffu, se, o);

#pragma unroll
    for (int i = 0; i < 8; i++)
        attn[(size_t)b * 256 + i * 32 + lane] = e[i] / se;
    if (lane == 0) cscore[b] = cs;

    float z[10];
#pragma unroll
    for (int jj = 0; jj < 10; jj++) z[jj] = 0.f;

    if (cs > 1e-4f) {
#pragma unroll
        for (int i = 0; i < 8; i++) {
            unsigned mask = __ballot_sync(0xffffffffu, e[i] > 0.f);
            while (mask) {
                int src = __ffs(mask) - 1;
                mask &= mask - 1;
                float aw = __shfl_sync(0xffffffffu, e[i], src) / se;
                int   tk = __shfl_sync(0xffffffffu, tok[i], src);
                const float* wr = w_emb + (size_t)tk * 300;
#pragma unroll
                for (int jj = 0; jj < 10; jj++) {
                    int j = jj * 32 + lane;
                    if (j < 300) z[jj] = fmaf(aw, wr[j], z[jj]);
                }
            }
        }
    }
#pragma unroll
    for (int jj = 0; jj < 10; jj++) {
        int j = jj * 32 + lane;
        if (j < 300) enc[(size_t)b * 300 + j] = z[jj];
    }
}

// ---------------- launch ----------------
extern "C" void kernel_launch(void* const* d_in, const int* in_sizes, int n_in,
                              void* d_out, int out_size) {
    const int*   inputs = (const int*)d_in[0];     // [B, L]
    const float* w_emb  = (const float*)d_in[1];   // [V, E]
    const float* a_emb  = (const float*)d_in[2];   // [A, E]
    const float* a_w    = (const float*)d_in[3];   // [A]

    int BL = in_sizes[0];
    int A  = in_sizes[3];
    int E  = in_sizes[2] / A;        // 300
    int V  = in_sizes[1] / E;        // 50000
    int L  = 256;
    int B  = BL / L;                 // 1024

    static bool attr_set = false;
    if (!attr_set) {
        cudaFuncSetAttribute(vocab_mma, cudaFuncAttributeMaxDynamicSharedMemorySize, SMEM_TOT);
        attr_set = true;
    }

    vocab_mma<<<(V + 127) / 128, 256, SMEM_TOT>>>(w_emb, a_emb, a_w, V);

    float* out    = (float*)d_out;
    float* enc    = out;                                   // [B, E]
    float* attn   = out + (size_t)B * E;                   // [B, L]
    float* cscore = out + (size_t)B * E + (size_t)B * L;   // [B]
    row_warp_kernel<<<B / 4, 128>>>(inputs, w_emb, enc, attn, cscore);
}